// round 10
// baseline (speedup 1.0000x reference)
#include <cuda_runtime.h>
#include <math.h>

#define FULL 0xFFFFFFFFu

#define CH_A 0.955f
#define CH_B 1.3693f
#define CH_INF 1e6f

#define RB 32            // rows per block
#define NB 16            // blocks per image
#define LEV 5            // doubling levels for T^RB

// ---- device scratch (no allocation allowed) ----
__device__ float    g_u[16 * 512 * 512];   // pass-1 tilted rows, then pass-2 tilted rows
__device__ float    g_F[16 * 512 * 512];   // pass-1 seed prefix term
__device__ float    g_S[16 * 512 * 512];   // pass-2 suffix term
__device__ float    g_bnd[16 * NB * 512];  // corrected block-boundary rows
__device__ int      g_dmaxb[16];           // per-image max distance (float bits, >=0)
__device__ int      g_hasfg[16];
__device__ float    g_acc[50];

__global__ void k_zero() {
    int i = threadIdx.x;
    if (i < 50) g_acc[i] = 0.0f;
    if (i < 16) g_dmaxb[i] = 0;
}

// ============================================================================
// Seeds + F builder fused: one CTA per image, 512 threads.
// Bitboard morphology -> seed board (in smem) -> carry table -> F to global.
// ============================================================================
__global__ void k_seedsF(const int* __restrict__ target) {
    extern __shared__ unsigned char smem_raw[];
    unsigned* maskb = (unsigned*)smem_raw;   // 8192 words
    unsigned* hdb   = maskb + 8192;          // later reused as carry table C
    unsigned* heb   = hdb + 8192;
    unsigned* bdb   = heb + 8192;

    const int img  = blockIdx.x;
    const int tid  = threadIdx.x;
    const int lane = tid & 31;
    const int warp = tid >> 5;
    const int* tg  = target + img * (512 * 512);

    // Phase A: int4 loads, nibble pack via segmented reduce
    const int rowsub  = tid >> 7;
    const int colbase = (warp & 3) * 128;
    const int col     = colbase + lane * 4;
    const int grp     = lane >> 3;
    const int sub     = lane & 7;
    const unsigned gm = 0xFFu << (grp * 8);
    unsigned anyfg = 0;
    #pragma unroll 4
    for (int it = 0; it < 128; ++it) {
        int row = it * 4 + rowsub;
        int4 v4 = *(const int4*)(tg + row * 512 + col);
        unsigned nib = (v4.x > 0 ? 1u : 0u) | (v4.y > 0 ? 2u : 0u)
                     | (v4.z > 0 ? 4u : 0u) | (v4.w > 0 ? 8u : 0u);
        anyfg |= nib;
        unsigned word = __reduce_or_sync(gm, nib << (sub * 4));
        if (sub == 0) maskb[row * 16 + (colbase >> 5) + grp] = word;
    }
    int has_fg = __syncthreads_or(anyfg != 0);

    // Phase B: horizontal dilate/erode
    #pragma unroll
    for (int k = 0; k < 16; ++k) {
        int i = tid + k * 512;
        int w = i & 15;
        unsigned cw  = maskb[i];
        unsigned pw  = (w > 0)  ? maskb[i - 1] : 0u;
        unsigned nw_ = (w < 15) ? maskb[i + 1] : 0u;
        unsigned ld = (cw << 1) | (pw >> 31);
        unsigned rd = (cw >> 1) | (nw_ << 31);
        hdb[i] = cw | ld | rd;
        unsigned le = (cw << 1) | ((w == 0)  ? 1u          : (pw >> 31));
        unsigned re = (cw >> 1) | ((w == 15) ? 0x80000000u : (nw_ << 31));
        heb[i] = cw & le & re;
    }
    __syncthreads();

    // Phase C: vertical combine -> boundary
    unsigned anyb = 0;
    #pragma unroll
    for (int k = 0; k < 16; ++k) {
        int i = tid + k * 512;
        int r = i >> 4;
        unsigned dil = hdb[i];
        unsigned ero = heb[i];
        if (r > 0)   { dil |= hdb[i - 16]; ero &= heb[i - 16]; }
        if (r < 511) { dil |= hdb[i + 16]; ero &= heb[i + 16]; }
        unsigned bd = dil & ~ero;
        bdb[i] = bd;
        anyb |= bd;
    }
    int has_b = __syncthreads_or(anyb != 0);

    // Phase D: seed words -> maskb (in place)
    #pragma unroll
    for (int k = 0; k < 16; ++k) {
        int i = tid + k * 512;
        maskb[i] = has_b ? bdb[i] : ~maskb[i];
    }
    __syncthreads();

    // Phase E: per-row carry table (thread = row); C reuses hdb storage
    int* C = (int*)hdb;
    {
        int cur = -1;
        #pragma unroll
        for (int w = 0; w < 16; ++w) {
            C[tid * 16 + w] = cur;
            unsigned word = maskb[tid * 16 + w];
            if (word) cur = w * 32 + 31 - __clz(word);
        }
    }
    __syncthreads();

    // Phase F: write F (float4-coalesced)
    float* Fimg = g_F + img * 262144;
    for (int qq = tid; qq < 65536; qq += 512) {
        int idx = qq * 4;
        int r = idx >> 9, j0 = idx & 511;
        int w = j0 >> 5;
        unsigned word = maskb[r * 16 + w];
        int carry = C[r * 16 + w];
        float4 o;
        #pragma unroll
        for (int e = 0; e < 4; ++e) {
            int j = j0 + e, b = j & 31;
            unsigned lb = word & (0xFFFFFFFFu >> (31 - b));
            int id = lb ? (w * 32 + 31 - __clz(lb)) : carry;
            (&o.x)[e] = (id >= 0) ? (-CH_A * (float)id) : CH_INF;
        }
        *(float4*)(Fimg + idx) = o;
    }
    if (tid == 0) g_hasfg[img] = has_fg;
}

static __device__ __forceinline__ void ldrow16(float* d, const float* p) {
    float4 a = *(const float4*)(p);
    float4 b = *(const float4*)(p + 4);
    float4 c = *(const float4*)(p + 8);
    float4 e = *(const float4*)(p + 12);
    d[0]=a.x; d[1]=a.y; d[2]=a.z; d[3]=a.w;
    d[4]=b.x; d[5]=b.y; d[6]=b.z; d[7]=b.w;
    d[8]=c.x; d[9]=c.y; d[10]=c.z; d[11]=c.w;
    d[12]=e.x; d[13]=e.y; d[14]=e.z; d[15]=e.w;
}
static __device__ __forceinline__ void strow16(float* p, const float* d) {
    *(float4*)(p)      = make_float4(d[0], d[1], d[2], d[3]);
    *(float4*)(p + 4)  = make_float4(d[4], d[5], d[6], d[7]);
    *(float4*)(p + 8)  = make_float4(d[8], d[9], d[10], d[11]);
    *(float4*)(p + 12) = make_float4(d[12], d[13], d[14], d[15]);
}

// ============================================================================
// Pass-1 local, PAIRED: warp handles blocks q and q+8. Grid 128 (one wave).
// ============================================================================
__global__ void __launch_bounds__(32, 1) k_local1() {
    const int img = blockIdx.x >> 3, q = blockIdx.x & 7;
    const int lane = threadIdx.x, c0 = lane * 16;
    const float* Fa = g_F + img * 262144 + q * RB * 512;
    const float* Fb = Fa + 8 * RB * 512;
    float* Ua = g_u + img * 262144 + q * RB * 512;
    float* Ub = Ua + 8 * RB * 512;

    float au[16], af[16], afn[16], anu[16];
    float bu[16], bf[16], bfn[16], bnu[16];
    #pragma unroll
    for (int j = 0; j < 16; ++j) { au[j] = CH_INF; bu[j] = CH_INF; }
    ldrow16(af,  Fa + c0);        ldrow16(bf,  Fb + c0);
    ldrow16(afn, Fa + 512 + c0);  ldrow16(bfn, Fb + 512 + c0);

    for (int r = 0; r < RB; ++r) {
        float aL = __shfl_up_sync(FULL, au[15], 1);
        float bL = __shfl_up_sync(FULL, bu[15], 1);
        float aR = __shfl_down_sync(FULL, au[0], 1);
        float bR = __shfl_down_sync(FULL, bu[0], 1);
        if (lane == 0)  { aL = CH_INF; bL = CH_INF; }
        if (lane == 31) { aR = CH_INF; bR = CH_INF; }
        #pragma unroll
        for (int j = 0; j < 16; ++j) {
            float la = (j == 0)  ? aL : au[j - 1];
            float ra = (j == 15) ? aR : au[j + 1];
            anu[j] = fminf(fminf(au[j] + CH_A, la + (CH_B - CH_A)),
                           fminf(ra + (CH_B + CH_A), af[j]));
            float lb = (j == 0)  ? bL : bu[j - 1];
            float rb = (j == 15) ? bR : bu[j + 1];
            bnu[j] = fminf(fminf(bu[j] + CH_A, lb + (CH_B - CH_A)),
                           fminf(rb + (CH_B + CH_A), bf[j]));
        }
        strow16(Ua + r * 512 + c0, anu);
        strow16(Ub + r * 512 + c0, bnu);
        int rp = min(r + 2, RB - 1);
        #pragma unroll
        for (int j = 0; j < 16; ++j) { au[j] = anu[j]; af[j] = afn[j]; bu[j] = bnu[j]; bf[j] = bfn[j]; }
        ldrow16(afn, Fa + rp * 512 + c0);
        ldrow16(bfn, Fb + rp * 512 + c0);
    }
}

// ============================================================================
// Pass-1 boundary: serial over 16 blocks; T^RB via doubling in shared.
// ============================================================================
__global__ void k_bnd1() {
    __shared__ float bb[512], wa[512], wb[512], wc[512], wd[512];
    const int img = blockIdx.x;
    const int j = threadIdx.x;
    const float* base = g_u + img * 262144;
    float* gb = g_bnd + img * NB * 512;

    bb[j] = base[(RB - 1) * 512 + j];
    gb[j] = bb[j];
    __syncthreads();

    for (int i = 1; i < NB; ++i) {
        wa[j] = bb[j]; wc[j] = bb[j];
        __syncthreads();
        float *Wr = wa, *Wr2 = wb, *Wl = wc, *Wl2 = wd;
        #pragma unroll
        for (int l = 0; l < LEV; ++l) {
            int s = 1 << l;
            Wr2[j] = fminf(Wr[j], (j >= s)      ? Wr[j - s] + (CH_B - CH_A) * (float)s : CH_INF);
            Wl2[j] = fminf(Wl[j], (j + s < 512) ? Wl[j + s] + (CH_B + CH_A) * (float)s : CH_INF);
            __syncthreads();
            float* t;
            t = Wr; Wr = Wr2; Wr2 = t;
            t = Wl; Wl = Wl2; Wl2 = t;
        }
        float corr = fminf(Wr[j], (j >= RB)       ? bb[j - RB] + (CH_B - CH_A) * (float)RB : CH_INF);
        corr = fminf(corr, fminf(Wl[j], (j + RB < 512) ? bb[j + RB] + (CH_B + CH_A) * (float)RB : CH_INF));
        corr += CH_A * (float)RB;
        float loc = base[(i * RB + RB - 1) * 512 + j];
        float nb = fminf(corr, loc);
        __syncthreads();
        bb[j] = nb;
        gb[i * 512 + j] = nb;
        __syncthreads();
    }
}

// ============================================================================
// Pass-1 fix, PAIRED: q<7 -> blocks (1+q, 9+q); q==7 -> block 8 only.
// ============================================================================
__global__ void __launch_bounds__(32, 1) k_fix1() {
    const int img = blockIdx.x >> 3, q = blockIdx.x & 7;
    const int lane = threadIdx.x, c0 = lane * 16;
    const float* gb = g_bnd + img * NB * 512;
    float* uimg = g_u + img * 262144;

    if (q < 7) {
        const int ba = 1 + q, bbk = 9 + q;
        float* Ua = uimg + ba * RB * 512;
        float* Ub = uimg + bbk * RB * 512;
        float av[16], anv[16], alo[16], aln[16];
        float bv[16], bnv[16], blo[16], bln[16];
        ldrow16(av, gb + (ba - 1) * 512 + c0);
        ldrow16(bv, gb + (bbk - 1) * 512 + c0);
        ldrow16(alo, Ua + c0);        ldrow16(blo, Ub + c0);
        ldrow16(aln, Ua + 512 + c0);  ldrow16(bln, Ub + 512 + c0);
        for (int r = 0; r < RB; ++r) {
            float aL = __shfl_up_sync(FULL, av[15], 1);
            float bL = __shfl_up_sync(FULL, bv[15], 1);
            float aR = __shfl_down_sync(FULL, av[0], 1);
            float bR = __shfl_down_sync(FULL, bv[0], 1);
            if (lane == 0)  { aL = CH_INF; bL = CH_INF; }
            if (lane == 31) { aR = CH_INF; bR = CH_INF; }
            #pragma unroll
            for (int j = 0; j < 16; ++j) {
                float la = (j == 0)  ? aL : av[j - 1];
                float ra = (j == 15) ? aR : av[j + 1];
                anv[j] = fminf(av[j] + CH_A, fminf(la + (CH_B - CH_A), ra + (CH_B + CH_A)));
                float lb = (j == 0)  ? bL : bv[j - 1];
                float rb = (j == 15) ? bR : bv[j + 1];
                bnv[j] = fminf(bv[j] + CH_A, fminf(lb + (CH_B - CH_A), rb + (CH_B + CH_A)));
            }
            float* pa = Ua + r * 512 + c0;
            float* pb = Ub + r * 512 + c0;
            #pragma unroll
            for (int k = 0; k < 4; ++k) {
                *(float4*)(pa + 4*k) = make_float4(fminf(anv[4*k],alo[4*k]), fminf(anv[4*k+1],alo[4*k+1]),
                                                   fminf(anv[4*k+2],alo[4*k+2]), fminf(anv[4*k+3],alo[4*k+3]));
                *(float4*)(pb + 4*k) = make_float4(fminf(bnv[4*k],blo[4*k]), fminf(bnv[4*k+1],blo[4*k+1]),
                                                   fminf(bnv[4*k+2],blo[4*k+2]), fminf(bnv[4*k+3],blo[4*k+3]));
            }
            int rp = min(r + 2, RB - 1);
            #pragma unroll
            for (int j = 0; j < 16; ++j) { av[j] = anv[j]; alo[j] = aln[j]; bv[j] = bnv[j]; blo[j] = bln[j]; }
            ldrow16(aln, Ua + rp * 512 + c0);
            ldrow16(bln, Ub + rp * 512 + c0);
        }
    } else {
        const int ba = 8;
        float* Ua = uimg + ba * RB * 512;
        float av[16], anv[16], alo[16], aln[16];
        ldrow16(av, gb + (ba - 1) * 512 + c0);
        ldrow16(alo, Ua + c0);
        ldrow16(aln, Ua + 512 + c0);
        for (int r = 0; r < RB; ++r) {
            float aL = __shfl_up_sync(FULL, av[15], 1); if (lane == 0)  aL = CH_INF;
            float aR = __shfl_down_sync(FULL, av[0], 1); if (lane == 31) aR = CH_INF;
            #pragma unroll
            for (int j = 0; j < 16; ++j) {
                float la = (j == 0)  ? aL : av[j - 1];
                float ra = (j == 15) ? aR : av[j + 1];
                anv[j] = fminf(av[j] + CH_A, fminf(la + (CH_B - CH_A), ra + (CH_B + CH_A)));
            }
            float* pa = Ua + r * 512 + c0;
            #pragma unroll
            for (int k = 0; k < 4; ++k)
                *(float4*)(pa + 4*k) = make_float4(fminf(anv[4*k],alo[4*k]), fminf(anv[4*k+1],alo[4*k+1]),
                                                   fminf(anv[4*k+2],alo[4*k+2]), fminf(anv[4*k+3],alo[4*k+3]));
            int rp = min(r + 2, RB - 1);
            #pragma unroll
            for (int j = 0; j < 16; ++j) { av[j] = anv[j]; alo[j] = aln[j]; }
            ldrow16(aln, Ua + rp * 512 + c0);
        }
    }
}

// ============================================================================
// Suffix-term builder: S[r][j] = min_{k>=j} (u1[r][k] + A*(2k-511)).
// ============================================================================
__global__ void k_suffix() {
    const int gw   = (blockIdx.x * 256 + threadIdx.x) >> 5;
    const int lane = threadIdx.x & 31;
    const int img  = gw >> 9, row = gw & 511;
    const float* u1 = g_u + img * 262144 + row * 512 + lane * 16;
    float* Sp       = g_S + img * 262144 + row * 512 + lane * 16;

    float nxc[16];
    #pragma unroll
    for (int k = 0; k < 4; ++k) {
        float4 t4 = *(const float4*)(u1 + 4 * k);
        int cb = lane * 16 + 4 * k;
        nxc[4*k]   = t4.x + CH_A * (float)(2 * (cb)     - 511);
        nxc[4*k+1] = t4.y + CH_A * (float)(2 * (cb + 1) - 511);
        nxc[4*k+2] = t4.z + CH_A * (float)(2 * (cb + 2) - 511);
        nxc[4*k+3] = t4.w + CH_A * (float)(2 * (cb + 3) - 511);
    }
    float s[16];
    s[15] = nxc[15];
    #pragma unroll
    for (int j = 14; j >= 0; --j) s[j] = fminf(s[j + 1], nxc[j]);
    float inc = s[0];
    #pragma unroll
    for (int o = 1; o < 32; o <<= 1) {
        float t = __shfl_down_sync(FULL, inc, o);
        if (lane + o < 32) inc = fminf(inc, t);
    }
    float exc = __shfl_down_sync(FULL, inc, 1);
    if (lane == 31) exc = CH_INF;
    #pragma unroll
    for (int k = 0; k < 4; ++k)
        *(float4*)(Sp + 4 * k) = make_float4(fminf(s[4*k], exc), fminf(s[4*k+1], exc),
                                             fminf(s[4*k+2], exc), fminf(s[4*k+3], exc));
}

// ============================================================================
// Pass-2 local, PAIRED (mirrored, bottom->top within block).
// ============================================================================
__global__ void __launch_bounds__(32, 1) k_local2() {
    const int img = blockIdx.x >> 3, q = blockIdx.x & 7;
    const int lane = threadIdx.x, c0 = lane * 16;
    const float* Sa = g_S + img * 262144 + q * RB * 512;
    const float* Sb = Sa + 8 * RB * 512;
    float* Ua = g_u + img * 262144 + q * RB * 512;
    float* Ub = Ua + 8 * RB * 512;

    float au[16], af[16], afn[16], anu[16];
    float bu[16], bf[16], bfn[16], bnu[16];
    #pragma unroll
    for (int j = 0; j < 16; ++j) { au[j] = CH_INF; bu[j] = CH_INF; }
    ldrow16(af,  Sa + (RB - 1) * 512 + c0);  ldrow16(bf,  Sb + (RB - 1) * 512 + c0);
    ldrow16(afn, Sa + (RB - 2) * 512 + c0);  ldrow16(bfn, Sb + (RB - 2) * 512 + c0);

    for (int i = 0; i < RB; ++i) {
        int r = RB - 1 - i;
        float aL = __shfl_up_sync(FULL, au[15], 1);
        float bL = __shfl_up_sync(FULL, bu[15], 1);
        float aR = __shfl_down_sync(FULL, au[0], 1);
        float bR = __shfl_down_sync(FULL, bu[0], 1);
        if (lane == 0)  { aL = CH_INF; bL = CH_INF; }
        if (lane == 31) { aR = CH_INF; bR = CH_INF; }
        #pragma unroll
        for (int j = 0; j < 16; ++j) {
            float la = (j == 0)  ? aL : au[j - 1];
            float ra = (j == 15) ? aR : au[j + 1];
            anu[j] = fminf(fminf(au[j] + CH_A, ra + (CH_B - CH_A)),
                           fminf(la + (CH_B + CH_A), af[j]));
            float lb = (j == 0)  ? bL : bu[j - 1];
            float rb = (j == 15) ? bR : bu[j + 1];
            bnu[j] = fminf(fminf(bu[j] + CH_A, rb + (CH_B - CH_A)),
                           fminf(lb + (CH_B + CH_A), bf[j]));
        }
        strow16(Ua + r * 512 + c0, anu);
        strow16(Ub + r * 512 + c0, bnu);
        int rp = RB - 1 - min(i + 2, RB - 1);
        #pragma unroll
        for (int j = 0; j < 16; ++j) { au[j] = anu[j]; af[j] = afn[j]; bu[j] = bnu[j]; bf[j] = bfn[j]; }
        ldrow16(afn, Sa + rp * 512 + c0);
        ldrow16(bfn, Sb + rp * 512 + c0);
    }
}

// ============================================================================
// Pass-2 boundary (mirrored slopes, blocks bottom-up).
// ============================================================================
__global__ void k_bnd2() {
    __shared__ float bb[512], wa[512], wb[512], wc[512], wd[512];
    const int img = blockIdx.x;
    const int j = threadIdx.x;
    const float* base = g_u + img * 262144;
    float* gb = g_bnd + img * NB * 512;

    bb[j] = base[((NB - 1) * RB) * 512 + j];
    gb[(NB - 1) * 512 + j] = bb[j];
    __syncthreads();

    for (int i = NB - 2; i >= 0; --i) {
        wa[j] = bb[j]; wc[j] = bb[j];
        __syncthreads();
        float *Wr = wa, *Wr2 = wb, *Wl = wc, *Wl2 = wd;
        #pragma unroll
        for (int l = 0; l < LEV; ++l) {
            int s = 1 << l;
            Wr2[j] = fminf(Wr[j], (j + s < 512) ? Wr[j + s] + (CH_B - CH_A) * (float)s : CH_INF);
            Wl2[j] = fminf(Wl[j], (j >= s)      ? Wl[j - s] + (CH_B + CH_A) * (float)s : CH_INF);
            __syncthreads();
            float* t;
            t = Wr; Wr = Wr2; Wr2 = t;
            t = Wl; Wl = Wl2; Wl2 = t;
        }
        float corr = fminf(Wr[j], (j + RB < 512) ? bb[j + RB] + (CH_B - CH_A) * (float)RB : CH_INF);
        corr = fminf(corr, fminf(Wl[j], (j >= RB) ? bb[j - RB] + (CH_B + CH_A) * (float)RB : CH_INF));
        corr += CH_A * (float)RB;
        float loc = base[(i * RB) * 512 + j];
        float nb = fminf(corr, loc);
        __syncthreads();
        bb[j] = nb;
        gb[i * 512 + j] = nb;
        __syncthreads();
    }
}

// ============================================================================
// Pass-2 fix, PAIRED + dmax fold. q<7 -> fix blocks (q, q+8); q==7 -> fix
// block 7 + max-only block 15.
// ============================================================================
__global__ void __launch_bounds__(32, 1) k_fix2() {
    const int img = blockIdx.x >> 3, q = blockIdx.x & 7;
    const int lane = threadIdx.x, c0 = lane * 16;
    const float* gb = g_bnd + img * NB * 512;
    float* uimg = g_u + img * 262144;

    float co[16];
    #pragma unroll
    for (int j = 0; j < 16; ++j) co[j] = CH_A * (float)(511 - (c0 + j));
    float dmx = 0.0f;

    if (q < 7) {
        const int ba = q, bbk = q + 8;
        float* Ua = uimg + ba * RB * 512;
        float* Ub = uimg + bbk * RB * 512;
        float av[16], anv[16], alo[16], aln[16];
        float bv[16], bnv[16], blo[16], bln[16];
        ldrow16(av, gb + (ba + 1) * 512 + c0);
        ldrow16(bv, gb + (bbk + 1) * 512 + c0);
        ldrow16(alo, Ua + (RB - 1) * 512 + c0);  ldrow16(blo, Ub + (RB - 1) * 512 + c0);
        ldrow16(aln, Ua + (RB - 2) * 512 + c0);  ldrow16(bln, Ub + (RB - 2) * 512 + c0);
        for (int i = 0; i < RB; ++i) {
            int r = RB - 1 - i;
            float aL = __shfl_up_sync(FULL, av[15], 1);
            float bL = __shfl_up_sync(FULL, bv[15], 1);
            float aR = __shfl_down_sync(FULL, av[0], 1);
            float bR = __shfl_down_sync(FULL, bv[0], 1);
            if (lane == 0)  { aL = CH_INF; bL = CH_INF; }
            if (lane == 31) { aR = CH_INF; bR = CH_INF; }
            #pragma unroll
            for (int j = 0; j < 16; ++j) {
                float la = (j == 0)  ? aL : av[j - 1];
                float ra = (j == 15) ? aR : av[j + 1];
                anv[j] = fminf(av[j] + CH_A, fminf(ra + (CH_B - CH_A), la + (CH_B + CH_A)));
                float lb = (j == 0)  ? bL : bv[j - 1];
                float rb = (j == 15) ? bR : bv[j + 1];
                bnv[j] = fminf(bv[j] + CH_A, fminf(rb + (CH_B - CH_A), lb + (CH_B + CH_A)));
            }
            float* pa = Ua + r * 512 + c0;
            float* pb = Ub + r * 512 + c0;
            #pragma unroll
            for (int k = 0; k < 4; ++k) {
                float o0 = fminf(anv[4*k],alo[4*k]),   o1 = fminf(anv[4*k+1],alo[4*k+1]);
                float o2 = fminf(anv[4*k+2],alo[4*k+2]), o3 = fminf(anv[4*k+3],alo[4*k+3]);
                *(float4*)(pa + 4*k) = make_float4(o0, o1, o2, o3);
                dmx = fmaxf(dmx, fmaxf(fmaxf(o0 + co[4*k], o1 + co[4*k+1]),
                                       fmaxf(o2 + co[4*k+2], o3 + co[4*k+3])));
                float p0 = fminf(bnv[4*k],blo[4*k]),   p1 = fminf(bnv[4*k+1],blo[4*k+1]);
                float p2 = fminf(bnv[4*k+2],blo[4*k+2]), p3 = fminf(bnv[4*k+3],blo[4*k+3]);
                *(float4*)(pb + 4*k) = make_float4(p0, p1, p2, p3);
                dmx = fmaxf(dmx, fmaxf(fmaxf(p0 + co[4*k], p1 + co[4*k+1]),
                                       fmaxf(p2 + co[4*k+2], p3 + co[4*k+3])));
            }
            int rp = RB - 1 - min(i + 2, RB - 1);
            #pragma unroll
            for (int j = 0; j < 16; ++j) { av[j] = anv[j]; alo[j] = aln[j]; bv[j] = bnv[j]; blo[j] = bln[j]; }
            ldrow16(aln, Ua + rp * 512 + c0);
            ldrow16(bln, Ub + rp * 512 + c0);
        }
    } else {
        // fix block 7
        {
            const int ba = 7;
            float* Ua = uimg + ba * RB * 512;
            float av[16], anv[16], alo[16], aln[16];
            ldrow16(av, gb + (ba + 1) * 512 + c0);
            ldrow16(alo, Ua + (RB - 1) * 512 + c0);
            ldrow16(aln, Ua + (RB - 2) * 512 + c0);
            for (int i = 0; i < RB; ++i) {
                int r = RB - 1 - i;
                float aL = __shfl_up_sync(FULL, av[15], 1); if (lane == 0)  aL = CH_INF;
                float aR = __shfl_down_sync(FULL, av[0], 1); if (lane == 31) aR = CH_INF;
                #pragma unroll
                for (int j = 0; j < 16; ++j) {
                    float la = (j == 0)  ? aL : av[j - 1];
                    float ra = (j == 15) ? aR : av[j + 1];
                    anv[j] = fminf(av[j] + CH_A, fminf(ra + (CH_B - CH_A), la + (CH_B + CH_A)));
                }
                float* pa = Ua + r * 512 + c0;
                #pragma unroll
                for (int k = 0; k < 4; ++k) {
                    float o0 = fminf(anv[4*k],alo[4*k]),   o1 = fminf(anv[4*k+1],alo[4*k+1]);
                    float o2 = fminf(anv[4*k+2],alo[4*k+2]), o3 = fminf(anv[4*k+3],alo[4*k+3]);
                    *(float4*)(pa + 4*k) = make_float4(o0, o1, o2, o3);
                    dmx = fmaxf(dmx, fmaxf(fmaxf(o0 + co[4*k], o1 + co[4*k+1]),
                                           fmaxf(o2 + co[4*k+2], o3 + co[4*k+3])));
                }
                int rp = RB - 1 - min(i + 2, RB - 1);
                #pragma unroll
                for (int j = 0; j < 16; ++j) { av[j] = anv[j]; alo[j] = aln[j]; }
                ldrow16(aln, Ua + rp * 512 + c0);
            }
        }
        // max-only block 15 (rows already final)
        {
            float* Ub = uimg + 15 * RB * 512;
            float rr[16];
            #pragma unroll 4
            for (int r = 0; r < RB; ++r) {
                ldrow16(rr, Ub + r * 512 + c0);
                #pragma unroll
                for (int j = 0; j < 16; ++j) dmx = fmaxf(dmx, rr[j] + co[j]);
            }
        }
    }

    #pragma unroll
    for (int o = 16; o >= 1; o >>= 1) dmx = fmaxf(dmx, __shfl_xor_sync(FULL, dmx, o));
    if (lane == 0) atomicMax(&g_dmaxb[img], __float_as_int(dmx));
}

// ============================================================================
// Elementwise losses + reductions (untilts u2 on the fly). Fast math.
// ============================================================================
__global__ void k_losses(const float* __restrict__ pred, const int* __restrict__ target) {
    const int img   = blockIdx.x >> 7;
    const int chunk = blockIdx.x & 127;
    const int base  = img * (512 * 512) + chunk * 2048;
    const int tid   = threadIdx.x;  // 256

    float mx  = __int_as_float(g_dmaxb[img]);
    float inv = (mx > 0.0f) ? (1.0f / fmaxf(mx, 1e-12f)) : 1.0f;
    int hfg   = g_hasfg[img];

    float s_focal = 0.f, s_bnd = 0.f, s_i = 0.f, s_p = 0.f, s_t = 0.f;

    #pragma unroll
    for (int k = 0; k < 2; ++k) {
        int i = base + (k * 256 + tid) * 4;
        float4 x4 = *(const float4*)(pred + i);
        int4   t4 = *(const int4*)(target + i);
        float4 u4 = *(const float4*)(g_u + i);
        int col = i & 511;
        #pragma unroll
        for (int e = 0; e < 4; ++e) {
            float x   = (&x4.x)[e];
            int   tgi = (&t4.x)[e];
            float dd  = (&u4.x)[e] + CH_A * (float)(511 - col - e);
            float t = (float)tgi;
            float ax = fabsf(x);
            float ee = __expf(-ax);
            float l  = __logf(1.0f + ee);
            float lsp = (x >= 0.f) ? -l : (x - l);
            float lsn = (x >= 0.f) ? (-x - l) : -l;
            float bce = -(t * lsp + (1.f - t) * lsn);
            float r1 = __fdividef(1.0f, 1.0f + ee);
            float p = (x >= 0.f) ? r1 : ee * r1;
            float pt = tgi ? p : (1.f - p);
            float at = tgi ? 0.25f : 0.75f;
            float om = 1.f - pt;
            s_focal += at * om * om * bce;
            s_i += p * t;
            s_p += p;
            s_t += t;
            float dn = dd * inv;
            float dist = hfg ? dn : 1.0f;
            s_bnd += (t * (1.f - p) + (1.f - t) * p) * (1.f + dist);
        }
    }

    #pragma unroll
    for (int o = 16; o >= 1; o >>= 1) {
        s_focal += __shfl_xor_sync(FULL, s_focal, o);
        s_bnd   += __shfl_xor_sync(FULL, s_bnd, o);
        s_i     += __shfl_xor_sync(FULL, s_i, o);
        s_p     += __shfl_xor_sync(FULL, s_p, o);
        s_t     += __shfl_xor_sync(FULL, s_t, o);
    }
    __shared__ float red[8][5];
    int lane = tid & 31, wid = tid >> 5;
    if (lane == 0) { red[wid][0]=s_focal; red[wid][1]=s_bnd; red[wid][2]=s_i; red[wid][3]=s_p; red[wid][4]=s_t; }
    __syncthreads();
    if (tid == 0) {
        float a0=0,a1=0,a2=0,a3=0,a4=0;
        #pragma unroll
        for (int k = 0; k < 8; ++k) { a0+=red[k][0]; a1+=red[k][1]; a2+=red[k][2]; a3+=red[k][3]; a4+=red[k][4]; }
        atomicAdd(&g_acc[0], a0);
        atomicAdd(&g_acc[1], a1);
        atomicAdd(&g_acc[2 + img], a2);
        atomicAdd(&g_acc[18 + img], a3);
        atomicAdd(&g_acc[34 + img], a4);
    }
}

// ============================================================================
// Final combine
// ============================================================================
__global__ void k_final(const float* __restrict__ log_vars, float* __restrict__ out) {
    if (threadIdx.x != 0) return;
    const float N = 16.0f * 512.0f * 512.0f;
    float focal = g_acc[0] / N;
    float bnd   = g_acc[1] / N;
    float dsum = 0.f, isum = 0.f;
    #pragma unroll
    for (int b = 0; b < 16; ++b) {
        float I = g_acc[2 + b];
        float T = g_acc[18 + b] + g_acc[34 + b];
        dsum += (2.0f * I + 1e-6f) / (T + 1e-6f);
        isum += (I + 1e-6f) / (T - I + 1e-6f);
    }
    float dice = 1.0f - dsum / 16.0f;
    float iou  = 1.0f - isum / 16.0f;
    float lv0 = log_vars[0], lv1 = log_vars[1], lv2 = log_vars[2], lv3 = log_vars[3];
    float total = expf(-lv0) * focal + lv0
                + expf(-lv1) * dice  + lv1
                + expf(-lv2) * bnd   + lv2
                + expf(-lv3) * iou   + lv3;
    out[0] = total; out[1] = focal; out[2] = dice; out[3] = bnd; out[4] = iou;
}

extern "C" void kernel_launch(void* const* d_in, const int* in_sizes, int n_in,
                              void* d_out, int out_size) {
    const float* pred     = (const float*)d_in[0];
    const int*   target   = (const int*)d_in[1];
    const float* log_vars = (const float*)d_in[2];
    float* out = (float*)d_out;

    const size_t smem_seeds = 4 * 8192 * sizeof(unsigned);
    cudaFuncSetAttribute(k_seedsF, cudaFuncAttributeMaxDynamicSharedMemorySize, (int)smem_seeds);

    k_zero<<<1, 64>>>();
    k_seedsF<<<16, 512, smem_seeds>>>(target);
    k_local1<<<128, 32>>>();
    k_bnd1<<<16, 512>>>();
    k_fix1<<<128, 32>>>();
    k_suffix<<<1024, 256>>>();
    k_local2<<<128, 32>>>();
    k_bnd2<<<16, 512>>>();
    k_fix2<<<128, 32>>>();
    k_losses<<<2048, 256>>>(pred, target);
    k_final<<<1, 32>>>(log_vars, out);
}

// round 11
// speedup vs baseline: 1.2020x; 1.2020x over previous
#include <cuda_runtime.h>
#include <math.h>

#define FULL 0xFFFFFFFFu

#define CH_A 0.955f
#define CH_B 1.3693f
#define CH_INF 1e6f

#define RB 32            // rows per block
#define NB 16            // blocks per image

// ---- device scratch (no allocation allowed) ----
__device__ float    g_u[16 * 512 * 512];   // pass-1 tilted rows, then pass-2 tilted rows
__device__ float    g_F[16 * 512 * 512];   // pass-1 seed prefix term
__device__ float    g_S[16 * 512 * 512];   // pass-2 suffix term
__device__ float    g_bnd[16 * NB * 512];  // corrected block-boundary rows
__device__ unsigned g_mask[16 * 8192];     // raw target bitboard (for k_losses)
__device__ int      g_dmaxb[16];           // per-image max distance (float bits, >=0)
__device__ int      g_hasfg[16];
__device__ float    g_acc[50];

__global__ void k_zero() {
    int i = threadIdx.x;
    if (i < 50) g_acc[i] = 0.0f;
    if (i < 16) g_dmaxb[i] = 0;
}

// ============================================================================
// Seeds + F builder fused: one CTA per image, 512 threads.
// ============================================================================
__global__ void k_seedsF(const int* __restrict__ target) {
    extern __shared__ unsigned char smem_raw[];
    unsigned* maskb = (unsigned*)smem_raw;   // 8192 words
    unsigned* hdb   = maskb + 8192;          // later reused as carry table C
    unsigned* heb   = hdb + 8192;
    unsigned* bdb   = heb + 8192;

    const int img  = blockIdx.x;
    const int tid  = threadIdx.x;
    const int lane = tid & 31;
    const int warp = tid >> 5;
    const int* tg  = target + img * (512 * 512);

    // Phase A: int4 loads, nibble pack via segmented reduce
    const int rowsub  = tid >> 7;
    const int colbase = (warp & 3) * 128;
    const int col     = colbase + lane * 4;
    const int grp     = lane >> 3;
    const int sub     = lane & 7;
    const unsigned gm = 0xFFu << (grp * 8);
    unsigned anyfg = 0;
    #pragma unroll 4
    for (int it = 0; it < 128; ++it) {
        int row = it * 4 + rowsub;
        int4 v4 = *(const int4*)(tg + row * 512 + col);
        unsigned nib = (v4.x > 0 ? 1u : 0u) | (v4.y > 0 ? 2u : 0u)
                     | (v4.z > 0 ? 4u : 0u) | (v4.w > 0 ? 8u : 0u);
        anyfg |= nib;
        unsigned word = __reduce_or_sync(gm, nib << (sub * 4));
        if (sub == 0) maskb[row * 16 + (colbase >> 5) + grp] = word;
    }
    int has_fg = __syncthreads_or(anyfg != 0);

    // Phase B: horizontal dilate/erode; also export raw mask board
    unsigned* gmk = g_mask + img * 8192;
    #pragma unroll
    for (int k = 0; k < 16; ++k) {
        int i = tid + k * 512;
        int w = i & 15;
        unsigned cw  = maskb[i];
        gmk[i] = cw;
        unsigned pw  = (w > 0)  ? maskb[i - 1] : 0u;
        unsigned nw_ = (w < 15) ? maskb[i + 1] : 0u;
        unsigned ld = (cw << 1) | (pw >> 31);
        unsigned rd = (cw >> 1) | (nw_ << 31);
        hdb[i] = cw | ld | rd;
        unsigned le = (cw << 1) | ((w == 0)  ? 1u          : (pw >> 31));
        unsigned re = (cw >> 1) | ((w == 15) ? 0x80000000u : (nw_ << 31));
        heb[i] = cw & le & re;
    }
    __syncthreads();

    // Phase C: vertical combine -> boundary
    unsigned anyb = 0;
    #pragma unroll
    for (int k = 0; k < 16; ++k) {
        int i = tid + k * 512;
        int r = i >> 4;
        unsigned dil = hdb[i];
        unsigned ero = heb[i];
        if (r > 0)   { dil |= hdb[i - 16]; ero &= heb[i - 16]; }
        if (r < 511) { dil |= hdb[i + 16]; ero &= heb[i + 16]; }
        unsigned bd = dil & ~ero;
        bdb[i] = bd;
        anyb |= bd;
    }
    int has_b = __syncthreads_or(anyb != 0);

    // Phase D: seed words -> maskb (in place)
    #pragma unroll
    for (int k = 0; k < 16; ++k) {
        int i = tid + k * 512;
        maskb[i] = has_b ? bdb[i] : ~maskb[i];
    }
    __syncthreads();

    // Phase E: per-row carry table (thread = row); C reuses hdb storage
    int* C = (int*)hdb;
    {
        int cur = -1;
        #pragma unroll
        for (int w = 0; w < 16; ++w) {
            C[tid * 16 + w] = cur;
            unsigned word = maskb[tid * 16 + w];
            if (word) cur = w * 32 + 31 - __clz(word);
        }
    }
    __syncthreads();

    // Phase F: write F (float4-coalesced)
    float* Fimg = g_F + img * 262144;
    for (int qq = tid; qq < 65536; qq += 512) {
        int idx = qq * 4;
        int r = idx >> 9, j0 = idx & 511;
        int w = j0 >> 5;
        unsigned word = maskb[r * 16 + w];
        int carry = C[r * 16 + w];
        float4 o;
        #pragma unroll
        for (int e = 0; e < 4; ++e) {
            int j = j0 + e, b = j & 31;
            unsigned lb = word & (0xFFFFFFFFu >> (31 - b));
            int id = lb ? (w * 32 + 31 - __clz(lb)) : carry;
            (&o.x)[e] = (id >= 0) ? (-CH_A * (float)id) : CH_INF;
        }
        *(float4*)(Fimg + idx) = o;
    }
    if (tid == 0) g_hasfg[img] = has_fg;
}

static __device__ __forceinline__ void ldrow16(float* d, const float* p) {
    float4 a = *(const float4*)(p);
    float4 b = *(const float4*)(p + 4);
    float4 c = *(const float4*)(p + 8);
    float4 e = *(const float4*)(p + 12);
    d[0]=a.x; d[1]=a.y; d[2]=a.z; d[3]=a.w;
    d[4]=b.x; d[5]=b.y; d[6]=b.z; d[7]=b.w;
    d[8]=c.x; d[9]=c.y; d[10]=c.z; d[11]=c.w;
    d[12]=e.x; d[13]=e.y; d[14]=e.z; d[15]=e.w;
}
static __device__ __forceinline__ void strow16(float* p, const float* d) {
    *(float4*)(p)      = make_float4(d[0], d[1], d[2], d[3]);
    *(float4*)(p + 4)  = make_float4(d[4], d[5], d[6], d[7]);
    *(float4*)(p + 8)  = make_float4(d[8], d[9], d[10], d[11]);
    *(float4*)(p + 12) = make_float4(d[12], d[13], d[14], d[15]);
}

// warp scans (inclusive)
static __device__ __forceinline__ float pscan_min(float x, int lane) {
    #pragma unroll
    for (int o = 1; o < 32; o <<= 1) {
        float v = __shfl_up_sync(FULL, x, o);
        if (lane >= o) x = fminf(x, v);
    }
    return x;
}
static __device__ __forceinline__ float sscan_min(float x, int lane) {
    #pragma unroll
    for (int o = 1; o < 32; o <<= 1) {
        float v = __shfl_down_sync(FULL, x, o);
        if (lane + o < 32) x = fminf(x, v);
    }
    return x;
}

// ============================================================================
// Pass-1 local: 1 warp per (image, block). 32-row recurrence from u=INF.
// ============================================================================
__global__ void __launch_bounds__(32, 1) k_local1() {
    const int img = blockIdx.x >> 4, blk = blockIdx.x & 15;
    const int lane = threadIdx.x, c0 = lane * 16;
    const float* Fb = g_F + img * 262144 + blk * RB * 512;
    float* ub = g_u + img * 262144 + blk * RB * 512;

    float u[16], f[16], fn[16], fn2[16], nu[16];
    #pragma unroll
    for (int j = 0; j < 16; ++j) u[j] = CH_INF;
    ldrow16(f,  Fb + c0);
    ldrow16(fn, Fb + 512 + c0);

    for (int r = 0; r < RB; ++r) {
        if (r < RB - 2) ldrow16(fn2, Fb + (r + 2) * 512 + c0);
        float uL = __shfl_up_sync(FULL, u[15], 1); if (lane == 0)  uL = CH_INF;
        float uR = __shfl_down_sync(FULL, u[0], 1); if (lane == 31) uR = CH_INF;
        #pragma unroll
        for (int j = 0; j < 16; ++j) {
            float left  = (j == 0)  ? uL : u[j - 1];
            float right = (j == 15) ? uR : u[j + 1];
            nu[j] = fminf(fminf(u[j] + CH_A, left + (CH_B - CH_A)),
                          fminf(right + (CH_B + CH_A), f[j]));
        }
        strow16(ub + r * 512 + c0, nu);
        #pragma unroll
        for (int j = 0; j < 16; ++j) { u[j] = nu[j]; f[j] = fn[j]; fn[j] = fn2[j]; }
    }
}

// ============================================================================
// Pass-1 boundary: 512 threads/image. Sliding-window T^RB via warp scans;
// ONE barrier per block-step (double-buffered cross-warp exchange).
// Window [j-32,j]: suffix(prev warp seg)+prefix(own); [j,j+32]: suffix(own)+prefix(next).
// ============================================================================
__global__ void k_bnd1() {
    __shared__ float sb_t[2][512], sb_s[2][512];
    const int img = blockIdx.x;
    const int j = threadIdx.x, lane = j & 31, w = j >> 5;
    const float* base = g_u + img * 262144;
    float* gb = g_bnd + img * NB * 512;
    const float c1 = CH_B - CH_A, c2 = CH_B + CH_A;
    const float c1j = c1 * (float)j, c2j = c2 * (float)j;

    float bb = base[(RB - 1) * 512 + j];
    gb[j] = bb;
    float loc = base[(RB + RB - 1) * 512 + j];

    for (int i = 1; i < NB; ++i) {
        float t = bb - c1j;                  // k<j direction, cost c1*(j-k)
        float s = bb + c2j;                  // k>j direction, cost c2*(k-j)
        float pre_t = pscan_min(t, lane);
        float suf_t = sscan_min(t, lane);
        float pre_s = pscan_min(s, lane);
        float suf_s = sscan_min(s, lane);
        int p = i & 1;
        sb_t[p][j] = suf_t;
        sb_s[p][j] = pre_s;
        float locn = (i + 1 < NB) ? base[((i + 1) * RB + RB - 1) * 512 + j] : 0.0f;
        __syncthreads();
        float suf_t_prev = (w > 0)  ? sb_t[p][j - 32] : CH_INF;
        float pre_s_next = (w < 15) ? sb_s[p][j + 32] : CH_INF;
        float wr = c1j + fminf(suf_t_prev, pre_t);
        float wl = fminf(suf_s, pre_s_next) - c2j;
        float nb = fminf(fminf(wr, wl) + CH_A * (float)RB, loc);
        bb = nb;
        gb[i * 512 + j] = nb;
        loc = locn;
    }
}

// ============================================================================
// Pass-1 fix: 1 warp per (image, block 1..NB-1). v <- T (x) v; merge local.
// ============================================================================
__global__ void __launch_bounds__(32, 1) k_fix1() {
    const int img = blockIdx.x / (NB - 1);
    const int blk = blockIdx.x % (NB - 1) + 1;
    const int lane = threadIdx.x, c0 = lane * 16;
    float* ub = g_u + img * 262144 + blk * RB * 512;

    float v[16], nv[16], loc[16], locn[16], locn2[16];
    ldrow16(v, g_bnd + (img * NB + blk - 1) * 512 + c0);
    ldrow16(loc,  ub + c0);
    ldrow16(locn, ub + 512 + c0);

    for (int r = 0; r < RB; ++r) {
        if (r < RB - 2) ldrow16(locn2, ub + (r + 2) * 512 + c0);
        float vL = __shfl_up_sync(FULL, v[15], 1); if (lane == 0)  vL = CH_INF;
        float vR = __shfl_down_sync(FULL, v[0], 1); if (lane == 31) vR = CH_INF;
        #pragma unroll
        for (int j = 0; j < 16; ++j) {
            float left  = (j == 0)  ? vL : v[j - 1];
            float right = (j == 15) ? vR : v[j + 1];
            nv[j] = fminf(v[j] + CH_A, fminf(left + (CH_B - CH_A), right + (CH_B + CH_A)));
        }
        float out[16];
        #pragma unroll
        for (int j = 0; j < 16; ++j) out[j] = fminf(nv[j], loc[j]);
        strow16(ub + r * 512 + c0, out);
        #pragma unroll
        for (int j = 0; j < 16; ++j) { v[j] = nv[j]; loc[j] = locn[j]; locn[j] = locn2[j]; }
    }
}

// ============================================================================
// Suffix-term builder: S[r][j] = min_{k>=j} (u1[r][k] + A*(2k-511)).
// ============================================================================
__global__ void k_suffix() {
    const int gw   = (blockIdx.x * 256 + threadIdx.x) >> 5;
    const int lane = threadIdx.x & 31;
    const int img  = gw >> 9, row = gw & 511;
    const float* u1 = g_u + img * 262144 + row * 512 + lane * 16;
    float* Sp       = g_S + img * 262144 + row * 512 + lane * 16;

    float nxc[16];
    #pragma unroll
    for (int k = 0; k < 4; ++k) {
        float4 t4 = *(const float4*)(u1 + 4 * k);
        int cb = lane * 16 + 4 * k;
        nxc[4*k]   = t4.x + CH_A * (float)(2 * (cb)     - 511);
        nxc[4*k+1] = t4.y + CH_A * (float)(2 * (cb + 1) - 511);
        nxc[4*k+2] = t4.z + CH_A * (float)(2 * (cb + 2) - 511);
        nxc[4*k+3] = t4.w + CH_A * (float)(2 * (cb + 3) - 511);
    }
    float s[16];
    s[15] = nxc[15];
    #pragma unroll
    for (int j = 14; j >= 0; --j) s[j] = fminf(s[j + 1], nxc[j]);
    float inc = sscan_min(s[0], lane);
    float exc = __shfl_down_sync(FULL, inc, 1);
    if (lane == 31) exc = CH_INF;
    #pragma unroll
    for (int k = 0; k < 4; ++k)
        *(float4*)(Sp + 4 * k) = make_float4(fminf(s[4*k], exc), fminf(s[4*k+1], exc),
                                             fminf(s[4*k+2], exc), fminf(s[4*k+3], exc));
}

// ============================================================================
// Pass-2 local (mirrored, bottom->top within block).
// ============================================================================
__global__ void __launch_bounds__(32, 1) k_local2() {
    const int img = blockIdx.x >> 4, blk = blockIdx.x & 15;
    const int lane = threadIdx.x, c0 = lane * 16;
    const float* Sb = g_S + img * 262144 + blk * RB * 512;
    float* ub = g_u + img * 262144 + blk * RB * 512;

    float u[16], f[16], fn[16], fn2[16], nu[16];
    #pragma unroll
    for (int j = 0; j < 16; ++j) u[j] = CH_INF;
    ldrow16(f,  Sb + (RB - 1) * 512 + c0);
    ldrow16(fn, Sb + (RB - 2) * 512 + c0);

    for (int r = RB - 1; r >= 0; --r) {
        if (r > 1) ldrow16(fn2, Sb + (r - 2) * 512 + c0);
        float uL = __shfl_up_sync(FULL, u[15], 1); if (lane == 0)  uL = CH_INF;
        float uR = __shfl_down_sync(FULL, u[0], 1); if (lane == 31) uR = CH_INF;
        #pragma unroll
        for (int j = 0; j < 16; ++j) {
            float left  = (j == 0)  ? uL : u[j - 1];
            float right = (j == 15) ? uR : u[j + 1];
            nu[j] = fminf(fminf(u[j] + CH_A, right + (CH_B - CH_A)),
                          fminf(left + (CH_B + CH_A), f[j]));
        }
        strow16(ub + r * 512 + c0, nu);
        #pragma unroll
        for (int j = 0; j < 16; ++j) { u[j] = nu[j]; f[j] = fn[j]; fn[j] = fn2[j]; }
    }
}

// ============================================================================
// Pass-2 boundary (mirrored: k>j costs c1*(k-j), k<j costs c2*(j-k)).
// ============================================================================
__global__ void k_bnd2() {
    __shared__ float sb_t[2][512], sb_s[2][512];
    const int img = blockIdx.x;
    const int j = threadIdx.x, lane = j & 31, w = j >> 5;
    const float* base = g_u + img * 262144;
    float* gb = g_bnd + img * NB * 512;
    const float c1 = CH_B - CH_A, c2 = CH_B + CH_A;
    const float c1j = c1 * (float)j, c2j = c2 * (float)j;

    float bb = base[((NB - 1) * RB) * 512 + j];
    gb[(NB - 1) * 512 + j] = bb;
    float loc = base[((NB - 2) * RB) * 512 + j];

    for (int i = NB - 2; i >= 0; --i) {
        float t = bb - c2j;                  // k<j direction, cost c2*(j-k)
        float s = bb + c1j;                  // k>j direction, cost c1*(k-j)
        float pre_t = pscan_min(t, lane);
        float suf_t = sscan_min(t, lane);
        float pre_s = pscan_min(s, lane);
        float suf_s = sscan_min(s, lane);
        int p = i & 1;
        sb_t[p][j] = suf_t;
        sb_s[p][j] = pre_s;
        float locn = (i > 0) ? base[((i - 1) * RB) * 512 + j] : 0.0f;
        __syncthreads();
        float suf_t_prev = (w > 0)  ? sb_t[p][j - 32] : CH_INF;
        float pre_s_next = (w < 15) ? sb_s[p][j + 32] : CH_INF;
        float wr = c2j + fminf(suf_t_prev, pre_t);
        float wl = fminf(suf_s, pre_s_next) - c1j;
        float nb = fminf(fminf(wr, wl) + CH_A * (float)RB, loc);
        bb = nb;
        gb[i * 512 + j] = nb;
        loc = locn;
    }
}

// ============================================================================
// Pass-2 fix + dmax fold. Grid 16*NB: blk<NB-1 fixes rows, blk==NB-1 max-only.
// ============================================================================
__global__ void __launch_bounds__(32, 1) k_fix2() {
    const int img = blockIdx.x >> 4;
    const int blk = blockIdx.x & 15;
    const int lane = threadIdx.x, c0 = lane * 16;
    float* ub = g_u + img * 262144 + blk * RB * 512;

    float co[16];
    #pragma unroll
    for (int j = 0; j < 16; ++j) co[j] = CH_A * (float)(511 - (c0 + j));

    float dmx = 0.0f;
    if (blk == NB - 1) {
        float rr[16];
        #pragma unroll 4
        for (int r = 0; r < RB; ++r) {
            ldrow16(rr, ub + r * 512 + c0);
            #pragma unroll
            for (int j = 0; j < 16; ++j) dmx = fmaxf(dmx, rr[j] + co[j]);
        }
    } else {
        float v[16], nv[16], loc[16], locn[16], locn2[16];
        ldrow16(v, g_bnd + (img * NB + blk + 1) * 512 + c0);
        ldrow16(loc,  ub + (RB - 1) * 512 + c0);
        ldrow16(locn, ub + (RB - 2) * 512 + c0);

        for (int r = RB - 1; r >= 0; --r) {
            if (r > 1) ldrow16(locn2, ub + (r - 2) * 512 + c0);
            float vL = __shfl_up_sync(FULL, v[15], 1); if (lane == 0)  vL = CH_INF;
            float vR = __shfl_down_sync(FULL, v[0], 1); if (lane == 31) vR = CH_INF;
            #pragma unroll
            for (int j = 0; j < 16; ++j) {
                float left  = (j == 0)  ? vL : v[j - 1];
                float right = (j == 15) ? vR : v[j + 1];
                nv[j] = fminf(v[j] + CH_A, fminf(right + (CH_B - CH_A), left + (CH_B + CH_A)));
            }
            float out[16];
            #pragma unroll
            for (int j = 0; j < 16; ++j) {
                out[j] = fminf(nv[j], loc[j]);
                dmx = fmaxf(dmx, out[j] + co[j]);
            }
            strow16(ub + r * 512 + c0, out);
            #pragma unroll
            for (int j = 0; j < 16; ++j) { v[j] = nv[j]; loc[j] = locn[j]; locn[j] = locn2[j]; }
        }
    }

    #pragma unroll
    for (int o = 16; o >= 1; o >>= 1) dmx = fmaxf(dmx, __shfl_xor_sync(FULL, dmx, o));
    if (lane == 0) atomicMax(&g_dmaxb[img], __float_as_int(dmx));
}

// ============================================================================
// Elementwise losses (target bits from g_mask bitboard; untilts u2 on the fly).
// ============================================================================
__global__ void k_losses(const float* __restrict__ pred) {
    const int img   = blockIdx.x >> 7;
    const int chunk = blockIdx.x & 127;
    const int tid   = threadIdx.x;  // 256

    float mx  = __int_as_float(g_dmaxb[img]);
    float inv = (mx > 0.0f) ? (1.0f / fmaxf(mx, 1e-12f)) : 1.0f;
    int hfg   = g_hasfg[img];
    const unsigned* gmk = g_mask + img * 8192;

    float s_focal = 0.f, s_bnd = 0.f, s_i = 0.f, s_p = 0.f, s_t = 0.f;

    #pragma unroll
    for (int k = 0; k < 2; ++k) {
        int li = chunk * 2048 + (k * 256 + tid) * 4;   // local element idx in image
        int i  = img * 262144 + li;
        float4 x4 = *(const float4*)(pred + i);
        float4 u4 = *(const float4*)(g_u + i);
        unsigned bits = (gmk[li >> 5] >> (li & 31)) & 0xFu;
        int col = li & 511;
        #pragma unroll
        for (int e = 0; e < 4; ++e) {
            float x   = (&x4.x)[e];
            int   tgi = (bits >> e) & 1;
            float dd  = (&u4.x)[e] + CH_A * (float)(511 - col - e);
            float t = (float)tgi;
            float ax = fabsf(x);
            float ee = __expf(-ax);
            float l  = __logf(1.0f + ee);
            float lsp = (x >= 0.f) ? -l : (x - l);
            float lsn = (x >= 0.f) ? (-x - l) : -l;
            float bce = -(t * lsp + (1.f - t) * lsn);
            float r1 = __fdividef(1.0f, 1.0f + ee);
            float p = (x >= 0.f) ? r1 : ee * r1;
            float pt = tgi ? p : (1.f - p);
            float at = tgi ? 0.25f : 0.75f;
            float om = 1.f - pt;
            s_focal += at * om * om * bce;
            s_i += p * t;
            s_p += p;
            s_t += t;
            float dn = dd * inv;
            float dist = hfg ? dn : 1.0f;
            s_bnd += (t * (1.f - p) + (1.f - t) * p) * (1.f + dist);
        }
    }

    #pragma unroll
    for (int o = 16; o >= 1; o >>= 1) {
        s_focal += __shfl_xor_sync(FULL, s_focal, o);
        s_bnd   += __shfl_xor_sync(FULL, s_bnd, o);
        s_i     += __shfl_xor_sync(FULL, s_i, o);
        s_p     += __shfl_xor_sync(FULL, s_p, o);
        s_t     += __shfl_xor_sync(FULL, s_t, o);
    }
    __shared__ float red[8][5];
    int lane = tid & 31, wid = tid >> 5;
    if (lane == 0) { red[wid][0]=s_focal; red[wid][1]=s_bnd; red[wid][2]=s_i; red[wid][3]=s_p; red[wid][4]=s_t; }
    __syncthreads();
    if (tid == 0) {
        float a0=0,a1=0,a2=0,a3=0,a4=0;
        #pragma unroll
        for (int k = 0; k < 8; ++k) { a0+=red[k][0]; a1+=red[k][1]; a2+=red[k][2]; a3+=red[k][3]; a4+=red[k][4]; }
        atomicAdd(&g_acc[0], a0);
        atomicAdd(&g_acc[1], a1);
        atomicAdd(&g_acc[2 + img], a2);
        atomicAdd(&g_acc[18 + img], a3);
        atomicAdd(&g_acc[34 + img], a4);
    }
}

// ============================================================================
// Final combine
// ============================================================================
__global__ void k_final(const float* __restrict__ log_vars, float* __restrict__ out) {
    if (threadIdx.x != 0) return;
    const float N = 16.0f * 512.0f * 512.0f;
    float focal = g_acc[0] / N;
    float bnd   = g_acc[1] / N;
    float dsum = 0.f, isum = 0.f;
    #pragma unroll
    for (int b = 0; b < 16; ++b) {
        float I = g_acc[2 + b];
        float T = g_acc[18 + b] + g_acc[34 + b];
        dsum += (2.0f * I + 1e-6f) / (T + 1e-6f);
        isum += (I + 1e-6f) / (T - I + 1e-6f);
    }
    float dice = 1.0f - dsum / 16.0f;
    float iou  = 1.0f - isum / 16.0f;
    float lv0 = log_vars[0], lv1 = log_vars[1], lv2 = log_vars[2], lv3 = log_vars[3];
    float total = expf(-lv0) * focal + lv0
                + expf(-lv1) * dice  + lv1
                + expf(-lv2) * bnd   + lv2
                + expf(-lv3) * iou   + lv3;
    out[0] = total; out[1] = focal; out[2] = dice; out[3] = bnd; out[4] = iou;
}

extern "C" void kernel_launch(void* const* d_in, const int* in_sizes, int n_in,
                              void* d_out, int out_size) {
    const float* pred     = (const float*)d_in[0];
    const float* log_vars = (const float*)d_in[2];
    float* out = (float*)d_out;

    const size_t smem_seeds = 4 * 8192 * sizeof(unsigned);
    cudaFuncSetAttribute(k_seedsF, cudaFuncAttributeMaxDynamicSharedMemorySize, (int)smem_seeds);

    k_zero<<<1, 64>>>();
    k_seedsF<<<16, 512, smem_seeds>>>((const int*)d_in[1]);
    k_local1<<<16 * NB, 32>>>();
    k_bnd1<<<16, 512>>>();
    k_fix1<<<16 * (NB - 1), 32>>>();
    k_suffix<<<1024, 256>>>();
    k_local2<<<16 * NB, 32>>>();
    k_bnd2<<<16, 512>>>();
    k_fix2<<<16 * NB, 32>>>();
    k_losses<<<2048, 256>>>(pred);
    k_final<<<1, 32>>>(log_vars, out);
}